// round 10
// baseline (speedup 1.0000x reference)
#include <cuda_runtime.h>
#include <cuda_fp16.h>
#include <cstdint>

// ---------------------------------------------------------------------------
// Problem constants
// ---------------------------------------------------------------------------
#define NN 100000
#define EE 1600000
#define HH 128
#define H2 256
#define GG 512
#define LL 3
#define BN_EPS 1e-5f
#define MTILES 782                    // ceil(100000/128)

// ---------------------------------------------------------------------------
// Scratch (device globals; no dynamic allocation allowed)
// ---------------------------------------------------------------------------
__device__ float g_z[(size_t)NN * HH];
__device__ float g_h[(size_t)NN * HH];
__device__ float g_t[(size_t)NN * H2];
__device__ float g_u[(size_t)NN * HH];
__device__ float g_f[(size_t)NN * HH];
__device__ float g_colsum[H2];
__device__ float g_colsq[H2];
__device__ float g_scaleA[H2];
__device__ float g_shiftA[H2];
__device__ float g_scaleB[HH];
__device__ float g_shiftB[HH];
__device__ float g_vf[GG * HH];
__device__ float g_pooled[GG * HH];
__device__ float g_vt2[GG * H2];
__device__ float g_vt1[GG * HH];
__device__ float g_counts[GG];
__device__ float g_vscale[H2];
__device__ float g_vshift[H2];
__device__ int   g_is64;
// fp16 3x-split weights, [n][k'] layout: W1' = [256][384], W2' = [128][768]
// k' pattern per original k: 3k = hi, 3k+1 = lo, 3k+2 = hi
__device__ __half g_w1h[LL * 256 * 384];
__device__ __half g_w2h[LL * 128 * 768];

// ---------------------------------------------------------------------------
// dtype detect (int64 vs int32 indices)
// ---------------------------------------------------------------------------
__global__ void detect_kernel(const int* __restrict__ ei32, int* __restrict__ flag) {
    __shared__ int any;
    if (threadIdx.x == 0) any = 0;
    __syncthreads();
    int v = ei32[2 * threadIdx.x + 1];
    if (v != 0) atomicOr(&any, 1);
    __syncthreads();
    if (threadIdx.x == 0) *flag = any ? 0 : 1;
}
__device__ __forceinline__ int load_index(const void* __restrict__ p, size_t i, int is64) {
    if (is64) return (int)reinterpret_cast<const long long*>(p)[i];
    return reinterpret_cast<const int*>(p)[i];
}

// ---------------------------------------------------------------------------
// fp16 split helper: a ~= hi + lo, hi/lo fp16
// ---------------------------------------------------------------------------
__device__ __forceinline__ void fp16_split(float a, __half& hi, __half& lo) {
    hi = __float2half_rn(a);
    lo = __float2half_rn(a - __half2float(hi));
}

// ---------------------------------------------------------------------------
// Weight conversion to [n][3K] fp16 rows (hi, lo, hi per original k)
// ---------------------------------------------------------------------------
__global__ void convw_kernel(const float* __restrict__ w1, const float* __restrict__ w2,
                             __half* __restrict__ o1, __half* __restrict__ o2) {
    int idx = blockIdx.x * blockDim.x + threadIdx.x;
    if (idx >= LL * HH * H2) return;
    int l = idx / (HH * H2);
    int rem = idx % (HH * H2);
    {   // W1[l][k][n] (k<128, n<256) -> o1[l][n][3k..3k+2]
        int k = rem >> 8, n = rem & 255;
        __half hi, lo;
        fp16_split(w1[idx], hi, lo);
        __half* base = o1 + (size_t)l * 256 * 384 + (size_t)n * 384;
        base[3 * k + 0] = hi;
        base[3 * k + 1] = lo;
        base[3 * k + 2] = hi;
    }
    {   // W2[l][kk][n] (kk<256, n<128) -> o2[l][n][3kk..3kk+2]
        int kk = rem >> 7, n = rem & 127;
        __half hi, lo;
        fp16_split(w2[idx], hi, lo);
        __half* base = o2 + (size_t)l * 128 * 768 + (size_t)n * 768;
        base[3 * kk + 0] = hi;
        base[3 * kk + 1] = lo;
        base[3 * kk + 2] = hi;
    }
}

// ---------------------------------------------------------------------------
// 3xFP16 mma.sync GEMM: out[M,CN] = act(A)[M,K] @ W + bias
// A k' pattern [hi,hi,lo] x W pattern [hi,lo,hi] => hi*hi + hi*lo + lo*hi.
// m16n8k16 fp16 mma, fp32 accum. Tile 128x128, 8 warps (4x2), chunk = 32 k.
// Fused BN column stats of output -> statsum/statsq (global atomics).
// TRANS: BN+ReLU fused into A split (GEMM2).
// ---------------------------------------------------------------------------
#define AS_STRIDE 104                 // halves; 208B rows, conflict-free + 16B aligned
#define SM_BYTES (26624 * 2 + 2048 + 512)

template <int KCH, int CN, bool TRANS>
__global__ void __launch_bounds__(256)
mma_gemm(const float* __restrict__ A, const __half* __restrict__ Bw,
         const float* __restrict__ bias, float* __restrict__ out, int M,
         const float* __restrict__ tsc, const float* __restrict__ tsh,
         float* __restrict__ statsum, float* __restrict__ statsq) {
    extern __shared__ char smem[];
    __half* A_s = (__half*)smem;                       // [128][104]
    __half* B_s = (__half*)(smem + 26624);             // [128][104]
    float* s_scale = (float*)(smem + 53248);           // [256]
    float* s_shift = s_scale + 256;                    // [256]
    float* s_bias = (float*)(smem + 53248 + 2048);     // [128]

    const int K = KCH * 32;            // original K
    const int K3 = K * 3;
    int tid = threadIdx.x;
    int lane = tid & 31;
    int warp = tid >> 5;
    int wr = warp >> 1;                // 0..3 (32-row group)
    int wc = warp & 1;                 // 0..1 (64-col group)
    int row0 = blockIdx.x * 128;
    int col0 = blockIdx.y * 128;

    if (TRANS) {
        for (int i = tid; i < K; i += 256) { s_scale[i] = tsc[i]; s_shift[i] = tsh[i]; }
    }
    if (tid < 128) s_bias[tid] = bias[col0 + tid];

    // prefetch registers: A 4 float4, B 6 float4 per thread
    float4 ga[4], gb[6];
    auto loadG = [&](int ch) {
#pragma unroll
        for (int i = 0; i < 4; i++) {
            int idx = tid + 256 * i;           // < 1024
            int row = idx >> 3, q = idx & 7;   // 8 float4 per 32-k row
            float4 v = make_float4(0.f, 0.f, 0.f, 0.f);
            if (row0 + row < M)
                v = *reinterpret_cast<const float4*>(
                    &A[(size_t)(row0 + row) * K + ch * 32 + q * 4]);
            ga[i] = v;
        }
#pragma unroll
        for (int r = 0; r < 6; r++) {
            int idx = tid + 256 * r;           // < 1536
            int n = idx / 12, f4 = idx % 12;
            gb[r] = *reinterpret_cast<const float4*>(
                Bw + (size_t)(col0 + n) * K3 + ch * 96 + f4 * 8);
        }
    };
    auto storeS = [&](int ch) {
#pragma unroll
        for (int i = 0; i < 4; i++) {
            int idx = tid + 256 * i;
            int row = idx >> 3, q = idx & 7;
            float f[4] = {ga[i].x, ga[i].y, ga[i].z, ga[i].w};
            __half h[12];
#pragma unroll
            for (int j = 0; j < 4; j++) {
                float a = f[j];
                if (TRANS) {
                    int kk = ch * 32 + q * 4 + j;
                    a = fmaxf(a * s_scale[kk] + s_shift[kk], 0.f);
                }
                __half hi, lo;
                fp16_split(a, hi, lo);
                h[3 * j + 0] = hi;
                h[3 * j + 1] = hi;
                h[3 * j + 2] = lo;
            }
            // 12 halves = 3 x uint2, 8B-aligned (row*208 + 24q)
            uint2* dst = reinterpret_cast<uint2*>(&A_s[row * AS_STRIDE + q * 12]);
            uint32_t w[6];
#pragma unroll
            for (int p = 0; p < 6; p++) {
                __half2 hp = __halves2half2(h[2 * p], h[2 * p + 1]);
                w[p] = *reinterpret_cast<uint32_t*>(&hp);
            }
            dst[0] = make_uint2(w[0], w[1]);
            dst[1] = make_uint2(w[2], w[3]);
            dst[2] = make_uint2(w[4], w[5]);
        }
#pragma unroll
        for (int r = 0; r < 6; r++) {
            int idx = tid + 256 * r;
            int n = idx / 12, f4 = idx % 12;
            *reinterpret_cast<float4*>(&B_s[n * AS_STRIDE + f4 * 8]) = gb[r];
        }
    };

    float acc[2][8][4];
#pragma unroll
    for (int mi = 0; mi < 2; mi++)
#pragma unroll
        for (int ni = 0; ni < 8; ni++)
#pragma unroll
            for (int q = 0; q < 4; q++) acc[mi][ni][q] = 0.f;

    loadG(0);
    __syncthreads();          // s_scale/s_bias visible
    storeS(0);

    for (int ch = 0; ch < KCH; ch++) {
        __syncthreads();      // smem tile ready
        if (ch + 1 < KCH) loadG(ch + 1);
        // 96 k' per chunk = 6 k16 steps
#pragma unroll
        for (int ks = 0; ks < 6; ks++) {
            int k0 = ks * 16;
            int coff = k0 + (lane & 3) * 2;
            uint32_t bfr[8][2];
            int bnr = lane >> 2;
#pragma unroll
            for (int ni = 0; ni < 8; ni++) {
                int n = wc * 64 + ni * 8 + bnr;
                bfr[ni][0] = *reinterpret_cast<uint32_t*>(&B_s[n * AS_STRIDE + coff]);
                bfr[ni][1] = *reinterpret_cast<uint32_t*>(&B_s[n * AS_STRIDE + coff + 8]);
            }
#pragma unroll
            for (int mi = 0; mi < 2; mi++) {
                int r = wr * 32 + mi * 16 + (lane >> 2);
                uint32_t a0 = *reinterpret_cast<uint32_t*>(&A_s[r * AS_STRIDE + coff]);
                uint32_t a1 = *reinterpret_cast<uint32_t*>(&A_s[(r + 8) * AS_STRIDE + coff]);
                uint32_t a2 = *reinterpret_cast<uint32_t*>(&A_s[r * AS_STRIDE + coff + 8]);
                uint32_t a3 = *reinterpret_cast<uint32_t*>(&A_s[(r + 8) * AS_STRIDE + coff + 8]);
#pragma unroll
                for (int ni = 0; ni < 8; ni++) {
                    asm volatile(
                        "mma.sync.aligned.m16n8k16.row.col.f32.f16.f16.f32 "
                        "{%0,%1,%2,%3}, {%4,%5,%6,%7}, {%8,%9}, {%0,%1,%2,%3};\n"
                        : "+f"(acc[mi][ni][0]), "+f"(acc[mi][ni][1]),
                          "+f"(acc[mi][ni][2]), "+f"(acc[mi][ni][3])
                        : "r"(a0), "r"(a1), "r"(a2), "r"(a3),
                          "r"(bfr[ni][0]), "r"(bfr[ni][1]));
                }
            }
        }
        __syncthreads();      // compute done before overwrite
        if (ch + 1 < KCH) storeS(ch + 1);
    }

    // --- epilogue: D + bias -> out ---
    int rb = row0 + wr * 32 + (lane >> 2);
    int cb = wc * 64 + (lane & 3) * 2;
#pragma unroll
    for (int mi = 0; mi < 2; mi++) {
        int r = rb + mi * 16;
#pragma unroll
        for (int ni = 0; ni < 8; ni++) {
            int cl = cb + ni * 8;
            float2 o0, o1;
            o0.x = acc[mi][ni][0] + s_bias[cl];
            o0.y = acc[mi][ni][1] + s_bias[cl + 1];
            o1.x = acc[mi][ni][2] + s_bias[cl];
            o1.y = acc[mi][ni][3] + s_bias[cl + 1];
            if (r < M)
                *reinterpret_cast<float2*>(&out[(size_t)r * CN + col0 + cl]) = o0;
            if (r + 8 < M)
                *reinterpret_cast<float2*>(&out[(size_t)(r + 8) * CN + col0 + cl]) = o1;
        }
    }

    // --- fused BN column stats (reuse A_s region for 128+128 floats) ---
    float* csum = (float*)smem;
    float* csq = csum + 128;
    if (tid < 128) { csum[tid] = 0.f; csq[tid] = 0.f; }
    __syncthreads();
#pragma unroll
    for (int ni = 0; ni < 8; ni++) {
        int cl = cb + ni * 8;
        float s0 = 0.f, q0 = 0.f, s1 = 0.f, q1 = 0.f;
#pragma unroll
        for (int mi = 0; mi < 2; mi++) {
            int r = rb + mi * 16;
            if (r < M) {
                float v = acc[mi][ni][0] + s_bias[cl];
                s0 += v; q0 += v * v;
                float w = acc[mi][ni][1] + s_bias[cl + 1];
                s1 += w; q1 += w * w;
            }
            if (r + 8 < M) {
                float v = acc[mi][ni][2] + s_bias[cl];
                s0 += v; q0 += v * v;
                float w = acc[mi][ni][3] + s_bias[cl + 1];
                s1 += w; q1 += w * w;
            }
        }
        atomicAdd(&csum[cl], s0);
        atomicAdd(&csq[cl], q0);
        atomicAdd(&csum[cl + 1], s1);
        atomicAdd(&csq[cl + 1], q1);
    }
    __syncthreads();
    if (tid < 128) {
        atomicAdd(&statsum[col0 + tid], csum[tid]);
        atomicAdd(&statsq[col0 + tid], csq[tid]);
    }
}

// ---------------------------------------------------------------------------
// init / copy
// ---------------------------------------------------------------------------
__global__ void init_kernel(const float* __restrict__ vn_emb, float* __restrict__ out_readout,
                            float* __restrict__ vf, float* __restrict__ pooled,
                            float* __restrict__ counts,
                            float* __restrict__ colsum, float* __restrict__ colsq) {
    int idx = blockIdx.x * blockDim.x + threadIdx.x;
    if (idx < GG * HH) {
        pooled[idx] = 0.f;
        out_readout[idx] = 0.f;
        vf[idx] = __ldg(&vn_emb[idx & (HH - 1)]);
    }
    if (idx < GG) counts[idx] = 0.f;
    if (idx < H2) { colsum[idx] = 0.f; colsq[idx] = 0.f; }
}

__global__ void copyz_kernel(const float* __restrict__ x, float* __restrict__ z) {
    size_t i = (size_t)blockIdx.x * blockDim.x + threadIdx.x;
    if (i < (size_t)NN * HH / 4)
        reinterpret_cast<float4*>(z)[i] = reinterpret_cast<const float4*>(x)[i];
}

// ---------------------------------------------------------------------------
// Edge scatter: 8 edges per warp, all gathers in flight before atomics
// ---------------------------------------------------------------------------
__global__ void scatter_kernel(const float* __restrict__ h, float* __restrict__ z,
                               const void* __restrict__ ei, int E,
                               const int* __restrict__ is64p) {
    int w = (int)(((size_t)blockIdx.x * blockDim.x + threadIdx.x) >> 5);
    int lane = threadIdx.x & 31;
    int Q = E >> 3;
    if (w >= Q) return;
    int is64 = *is64p;
    int src[8], dst[8];
#pragma unroll
    for (int e = 0; e < 8; e++) src[e] = load_index(ei, (size_t)(w + e * Q), is64);
#pragma unroll
    for (int e = 0; e < 8; e++) dst[e] = load_index(ei, (size_t)E + (w + e * Q), is64);
    float4 v[8];
#pragma unroll
    for (int e = 0; e < 8; e++)
        v[e] = *reinterpret_cast<const float4*>(&h[(size_t)src[e] * HH + lane * 4]);
#pragma unroll
    for (int e = 0; e < 8; e++)
        atomicAdd(reinterpret_cast<float4*>(&z[(size_t)dst[e] * HH + lane * 4]), v[e]);
}

// ---------------------------------------------------------------------------
// BN column stats (vn MLP only) + finalize
// ---------------------------------------------------------------------------
template <int C>
__global__ void colstats_kernel(const float* __restrict__ X, int Nrows,
                                float* __restrict__ sum, float* __restrict__ sq) {
    int c = threadIdx.x;
    float s = 0.f, q = 0.f;
    for (int r = blockIdx.x; r < Nrows; r += gridDim.x) {
        float v = X[(size_t)r * C + c];
        s += v;
        q += v * v;
    }
    atomicAdd(&sum[c], s);
    atomicAdd(&sq[c], q);
}

__global__ void bn_finalize_kernel(float* __restrict__ sum, float* __restrict__ sq,
                                   const float* __restrict__ g, const float* __restrict__ b,
                                   float* __restrict__ scale, float* __restrict__ shift,
                                   int C, float invN) {
    int c = threadIdx.x;
    if (c < C) {
        float m = sum[c] * invN;
        float v = sq[c] * invN - m * m;
        float sc = __ldg(&g[c]) * rsqrtf(v + BN_EPS);
        scale[c] = sc;
        shift[c] = __ldg(&b[c]) - m * sc;
        sum[c] = 0.f;
        sq[c] = 0.f;
    }
}

// ---------------------------------------------------------------------------
// Per-layer finalize / prep kernels
// ---------------------------------------------------------------------------
__global__ void prep0_kernel(const float* __restrict__ u, const float* __restrict__ sc,
                             const float* __restrict__ sh, const float* __restrict__ vn_emb,
                             float* __restrict__ h, float* __restrict__ z) {
    size_t idx = (size_t)blockIdx.x * blockDim.x + threadIdx.x;
    if (idx >= (size_t)NN * (HH / 4)) return;
    int c = (int)(idx & 31) * 4;
    float4 v = reinterpret_cast<const float4*>(u)[idx];
    float4 r;
    r.x = fmaxf(v.x * sc[c + 0] + sh[c + 0], 0.f) + __ldg(&vn_emb[c + 0]);
    r.y = fmaxf(v.y * sc[c + 1] + sh[c + 1], 0.f) + __ldg(&vn_emb[c + 1]);
    r.z = fmaxf(v.z * sc[c + 2] + sh[c + 2], 0.f) + __ldg(&vn_emb[c + 2]);
    r.w = fmaxf(v.w * sc[c + 3] + sh[c + 3], 0.f) + __ldg(&vn_emb[c + 3]);
    reinterpret_cast<float4*>(h)[idx] = r;
    reinterpret_cast<float4*>(z)[idx] = r;
}

__global__ void fin1_kernel(const float* __restrict__ u, const float* __restrict__ sc,
                            const float* __restrict__ sh, float* __restrict__ f,
                            const void* __restrict__ batch, float* __restrict__ pooled,
                            const int* __restrict__ is64p) {
    size_t idx = (size_t)blockIdx.x * blockDim.x + threadIdx.x;
    if (idx >= (size_t)NN * (HH / 4)) return;
    int n = (int)(idx >> 5);
    int c = (int)(idx & 31) * 4;
    float4 v = reinterpret_cast<const float4*>(u)[idx];
    float4 r;
    r.x = fmaxf(v.x * sc[c + 0] + sh[c + 0], 0.f);
    r.y = fmaxf(v.y * sc[c + 1] + sh[c + 1], 0.f);
    r.z = fmaxf(v.z * sc[c + 2] + sh[c + 2], 0.f);
    r.w = fmaxf(v.w * sc[c + 3] + sh[c + 3], 0.f);
    reinterpret_cast<float4*>(f)[idx] = r;
    int g = load_index(batch, n, *is64p);
    atomicAdd(reinterpret_cast<float4*>(&pooled[(size_t)g * HH + c]), r);
}

__global__ void prep1_kernel(const float* __restrict__ f, const float* __restrict__ vf,
                             const void* __restrict__ batch,
                             float* __restrict__ h, float* __restrict__ z,
                             const int* __restrict__ is64p) {
    size_t idx = (size_t)blockIdx.x * blockDim.x + threadIdx.x;
    if (idx >= (size_t)NN * (HH / 4)) return;
    int n = (int)(idx >> 5);
    int c = (int)(idx & 31) * 4;
    int g = load_index(batch, n, *is64p);
    float4 a = reinterpret_cast<const float4*>(f)[idx];
    float4 b = *reinterpret_cast<const float4*>(&vf[(size_t)g * HH + c]);
    float4 r;
    r.x = a.x + b.x; r.y = a.y + b.y; r.z = a.z + b.z; r.w = a.w + b.w;
    reinterpret_cast<float4*>(h)[idx] = r;
    reinterpret_cast<float4*>(z)[idx] = r;
}

__global__ void fin2_kernel(const float* __restrict__ u, const float* __restrict__ sc,
                            const float* __restrict__ sh, float* __restrict__ out_feats,
                            const void* __restrict__ batch,
                            float* __restrict__ readout, float* __restrict__ counts,
                            const int* __restrict__ is64p) {
    size_t idx = (size_t)blockIdx.x * blockDim.x + threadIdx.x;
    if (idx >= (size_t)NN * (HH / 4)) return;
    int n = (int)(idx >> 5);
    int c = (int)(idx & 31) * 4;
    float4 v = reinterpret_cast<const float4*>(u)[idx];
    float4 r;
    r.x = v.x * sc[c + 0] + sh[c + 0];
    r.y = v.y * sc[c + 1] + sh[c + 1];
    r.z = v.z * sc[c + 2] + sh[c + 2];
    r.w = v.w * sc[c + 3] + sh[c + 3];
    reinterpret_cast<float4*>(out_feats)[idx] = r;
    int g = load_index(batch, n, *is64p);
    atomicAdd(reinterpret_cast<float4*>(&readout[(size_t)g * HH + c]), r);
    if (c == 0) atomicAdd(&counts[g], 1.0f);
}

__global__ void epilogue_kernel(float* __restrict__ readout, const float* __restrict__ counts,
                                const float* __restrict__ vf, float* __restrict__ vf_out) {
    int idx = blockIdx.x * blockDim.x + threadIdx.x;
    if (idx < GG * HH) {
        float cnt = fmaxf(counts[idx >> 7], 1.0f);
        readout[idx] = readout[idx] / cnt;
        vf_out[idx] = vf[idx];
    }
}

// ---------------------------------------------------------------------------
// Virtual-node MLP kernels (tiny: G=512 rows)
// ---------------------------------------------------------------------------
__global__ void vgemm1_kernel(const float* __restrict__ pooled, const float* __restrict__ vf,
                              const float* __restrict__ W, const float* __restrict__ b,
                              float* __restrict__ out) {
    int g = blockIdx.x;
    int c = threadIdx.x;
    __shared__ float a[HH];
    if (c < HH) a[c] = pooled[g * HH + c] + vf[g * HH + c];
    __syncthreads();
    float acc = __ldg(&b[c]);
#pragma unroll 8
    for (int k = 0; k < HH; k++) acc = fmaf(a[k], __ldg(&W[k * H2 + c]), acc);
    out[g * H2 + c] = acc;
}

__global__ void vgemm2_kernel(const float* __restrict__ vt2, const float* __restrict__ vs,
                              const float* __restrict__ vsh, const float* __restrict__ W,
                              const float* __restrict__ b, float* __restrict__ out) {
    int g = blockIdx.x;
    int c = threadIdx.x;
    __shared__ float a[H2];
    for (int k = c; k < H2; k += HH)
        a[k] = fmaxf(vt2[g * H2 + k] * vs[k] + vsh[k], 0.f);
    __syncthreads();
    float acc = __ldg(&b[c]);
#pragma unroll 8
    for (int k = 0; k < H2; k++) acc = fmaf(a[k], __ldg(&W[k * HH + c]), acc);
    out[g * HH + c] = acc;
}

__global__ void vapply_kernel(const float* __restrict__ vt1, const float* __restrict__ vs,
                              const float* __restrict__ vsh, float* __restrict__ vf) {
    int idx = blockIdx.x * blockDim.x + threadIdx.x;
    if (idx < GG * HH) {
        int c = idx & (HH - 1);
        vf[idx] = fmaxf(vt1[idx] * vs[c] + vsh[c], 0.f);
    }
}

// ---------------------------------------------------------------------------
// Host driver
// ---------------------------------------------------------------------------
extern "C" void kernel_launch(void* const* d_in, const int* in_sizes, int n_in,
                              void* d_out, int out_size) {
    int off = (n_in > 3 && in_sizes[3] <= 4) ? 1 : 0;
    const float* x            = (const float*)d_in[0];
    const void*  ei           = d_in[1];
    const void*  batch        = d_in[2];
    const float* conv_w1      = (const float*)d_in[3 + off];
    const float* conv_b1      = (const float*)d_in[4 + off];
    const float* conv_bn_g    = (const float*)d_in[5 + off];
    const float* conv_bn_b    = (const float*)d_in[6 + off];
    const float* conv_w2      = (const float*)d_in[7 + off];
    const float* conv_b2      = (const float*)d_in[8 + off];
    const float* bn_g         = (const float*)d_in[9 + off];
    const float* bn_b         = (const float*)d_in[10 + off];
    const float* vn_emb       = (const float*)d_in[11 + off];
    const float* vmlp_w1      = (const float*)d_in[12 + off];
    const float* vmlp_b1      = (const float*)d_in[13 + off];
    const float* vmlp_bn1_g   = (const float*)d_in[14 + off];
    const float* vmlp_bn1_b   = (const float*)d_in[15 + off];
    const float* vmlp_w2      = (const float*)d_in[16 + off];
    const float* vmlp_b2      = (const float*)d_in[17 + off];
    const float* vmlp_bn2_g   = (const float*)d_in[18 + off];
    const float* vmlp_bn2_b   = (const float*)d_in[19 + off];

    float* out = (float*)d_out;
    float* out_feats = out;
    float* out_readout = out + (size_t)NN * HH;
    float* out_vf = out_readout + GG * HH;

    float *p_z, *p_h, *p_t, *p_u, *p_f, *p_colsum, *p_colsq, *p_scaleA, *p_shiftA,
          *p_scaleB, *p_shiftB, *p_vf, *p_pooled, *p_vt2, *p_vt1, *p_counts,
          *p_vscale, *p_vshift;
    __half *p_w1h, *p_w2h;
    int* p_is64;
    cudaGetSymbolAddress((void**)&p_z, g_z);
    cudaGetSymbolAddress((void**)&p_h, g_h);
    cudaGetSymbolAddress((void**)&p_t, g_t);
    cudaGetSymbolAddress((void**)&p_u, g_u);
    cudaGetSymbolAddress((void**)&p_f, g_f);
    cudaGetSymbolAddress((void**)&p_colsum, g_colsum);
    cudaGetSymbolAddress((void**)&p_colsq, g_colsq);
    cudaGetSymbolAddress((void**)&p_scaleA, g_scaleA);
    cudaGetSymbolAddress((void**)&p_shiftA, g_shiftA);
    cudaGetSymbolAddress((void**)&p_scaleB, g_scaleB);
    cudaGetSymbolAddress((void**)&p_shiftB, g_shiftB);
    cudaGetSymbolAddress((void**)&p_vf, g_vf);
    cudaGetSymbolAddress((void**)&p_pooled, g_pooled);
    cudaGetSymbolAddress((void**)&p_vt2, g_vt2);
    cudaGetSymbolAddress((void**)&p_vt1, g_vt1);
    cudaGetSymbolAddress((void**)&p_counts, g_counts);
    cudaGetSymbolAddress((void**)&p_vscale, g_vscale);
    cudaGetSymbolAddress((void**)&p_vshift, g_vshift);
    cudaGetSymbolAddress((void**)&p_is64, g_is64);
    cudaGetSymbolAddress((void**)&p_w1h, g_w1h);
    cudaGetSymbolAddress((void**)&p_w2h, g_w2h);

    cudaFuncSetAttribute(mma_gemm<4, H2, false>,
                         cudaFuncAttributeMaxDynamicSharedMemorySize, SM_BYTES);
    cudaFuncSetAttribute(mma_gemm<8, HH, true>,
                         cudaFuncAttributeMaxDynamicSharedMemorySize, SM_BYTES);

    const int M = NN;
    const float invN = 1.0f / (float)NN;
    const float invG = 1.0f / (float)GG;
    int ew_blocks = (NN * (HH / 4) + 255) / 256;
    int sc_blocks = ((EE / 8) + 7) / 8;     // 8 edges per warp, 8 warps/block

    detect_kernel<<<1, 1024>>>((const int*)ei, p_is64);
    convw_kernel<<<(LL * HH * H2 + 255) / 256, 256>>>(conv_w1, conv_w2, p_w1h, p_w2h);
    init_kernel<<<(GG * HH + 255) / 256, 256>>>(vn_emb, out_readout, p_vf, p_pooled,
                                                p_counts, p_colsum, p_colsq);
    copyz_kernel<<<(NN * HH / 4 + 255) / 256, 256>>>(x, p_z);

    for (int l = 0; l < LL; l++) {
        const float* b1 = conv_b1 + l * H2;
        const float* cg = conv_bn_g + l * H2;
        const float* cb = conv_bn_b + l * H2;
        const float* b2 = conv_b2 + l * HH;
        const float* og = bn_g + l * HH;
        const float* ob = bn_b + l * HH;
        const __half* w1h = p_w1h + (size_t)l * 256 * 384;
        const __half* w2h = p_w2h + (size_t)l * 128 * 768;

        const float* hsrc = (l == 0) ? x : p_h;
        scatter_kernel<<<sc_blocks, 256>>>(hsrc, p_z, ei, EE, p_is64);

        // GEMM1: t = z @ W1 + b1   (3xFP16 mma, K=128 -> 4 chunks, CN=256; fused stats)
        mma_gemm<4, H2, false><<<dim3(MTILES, 2), 256, SM_BYTES>>>(
            p_z, w1h, b1, p_t, M, nullptr, nullptr, p_colsum, p_colsq);
        bn_finalize_kernel<<<1, 256>>>(p_colsum, p_colsq, cg, cb, p_scaleA, p_shiftA,
                                       H2, invN);

        // GEMM2: u = relu(bn(t)) @ W2 + b2  (K=256 -> 8 chunks, CN=128; fused stats)
        mma_gemm<8, HH, true><<<dim3(MTILES, 1), 256, SM_BYTES>>>(
            p_t, w2h, b2, p_u, M, p_scaleA, p_shiftA, p_colsum, p_colsq);
        bn_finalize_kernel<<<1, 256>>>(p_colsum, p_colsq, og, ob, p_scaleB, p_shiftB,
                                       HH, invN);

        if (l == 0) {
            prep0_kernel<<<ew_blocks, 256>>>(p_u, p_scaleB, p_shiftB, vn_emb, p_h, p_z);
        } else if (l == 1) {
            fin1_kernel<<<ew_blocks, 256>>>(p_u, p_scaleB, p_shiftB, p_f, batch, p_pooled,
                                            p_is64);
            vgemm1_kernel<<<GG, H2>>>(p_pooled, p_vf, vmlp_w1, vmlp_b1, p_vt2);
            colstats_kernel<H2><<<64, H2>>>(p_vt2, GG, p_colsum, p_colsq);
            bn_finalize_kernel<<<1, 256>>>(p_colsum, p_colsq, vmlp_bn1_g, vmlp_bn1_b,
                                           p_vscale, p_vshift, H2, invG);
            vgemm2_kernel<<<GG, HH>>>(p_vt2, p_vscale, p_vshift, vmlp_w2, vmlp_b2, p_vt1);
            colstats_kernel<HH><<<64, HH>>>(p_vt1, GG, p_colsum, p_colsq);
            bn_finalize_kernel<<<1, 256>>>(p_colsum, p_colsq, vmlp_bn2_g, vmlp_bn2_b,
                                           p_vscale, p_vshift, HH, invG);
            vapply_kernel<<<(GG * HH + 255) / 256, 256>>>(p_vt1, p_vscale, p_vshift, p_vf);
            prep1_kernel<<<ew_blocks, 256>>>(p_f, p_vf, batch, p_h, p_z, p_is64);
        } else {
            fin2_kernel<<<ew_blocks, 256>>>(p_u, p_scaleB, p_shiftB, out_feats, batch,
                                            out_readout, p_counts, p_is64);
        }
    }

    epilogue_kernel<<<(GG * HH + 255) / 256, 256>>>(out_readout, p_counts, p_vf, out_vf);
    (void)in_sizes; (void)n_in; (void)out_size;
}

// round 11
// speedup vs baseline: 1.2213x; 1.2213x over previous
#include <cuda_runtime.h>
#include <cstdint>

// ---------------------------------------------------------------------------
// Problem constants
// ---------------------------------------------------------------------------
#define NN 100000
#define EE 1600000
#define HH 128
#define H2 256
#define GG 512
#define LL 3
#define BN_EPS 1e-5f

// ---------------------------------------------------------------------------
// Scratch (device globals; no dynamic allocation allowed)
// ---------------------------------------------------------------------------
__device__ float g_z[(size_t)NN * HH];
__device__ float g_h[(size_t)NN * HH];
__device__ float g_t[(size_t)NN * H2];
__device__ float g_u[(size_t)NN * HH];
__device__ float g_f[(size_t)NN * HH];
__device__ float g_colsum[H2];
__device__ float g_colsq[H2];
__device__ float g_scaleA[H2];
__device__ float g_shiftA[H2];
__device__ float g_scaleB[HH];
__device__ float g_shiftB[HH];
__device__ float g_vf[GG * HH];
__device__ float g_pooled[GG * HH];
__device__ float g_vt2[GG * H2];
__device__ float g_vt1[GG * HH];
__device__ float g_counts[GG];
__device__ float g_vscale[H2];
__device__ float g_vshift[H2];
__device__ int   g_is64;

// ---------------------------------------------------------------------------
// dtype detect: int64 nonneg values < 2^31 have zero high (odd) 32-bit words.
// ---------------------------------------------------------------------------
__global__ void detect_kernel(const int* __restrict__ ei32, int* __restrict__ flag) {
    __shared__ int any;
    if (threadIdx.x == 0) any = 0;
    __syncthreads();
    int v = ei32[2 * threadIdx.x + 1];
    if (v != 0) atomicOr(&any, 1);
    __syncthreads();
    if (threadIdx.x == 0) *flag = any ? 0 : 1;
}

__device__ __forceinline__ int load_index(const void* __restrict__ p, size_t i, int is64) {
    if (is64) return (int)reinterpret_cast<const long long*>(p)[i];
    return reinterpret_cast<const int*>(p)[i];
}

// ---------------------------------------------------------------------------
// init
// ---------------------------------------------------------------------------
__global__ void init_kernel(const float* __restrict__ vn_emb,
                            float* __restrict__ out_readout,
                            float* __restrict__ vf, float* __restrict__ pooled,
                            float* __restrict__ counts,
                            float* __restrict__ colsum, float* __restrict__ colsq) {
    int idx = blockIdx.x * blockDim.x + threadIdx.x;
    if (idx < GG * HH) {
        pooled[idx] = 0.f;
        out_readout[idx] = 0.f;
        vf[idx] = __ldg(&vn_emb[idx & (HH - 1)]);
    }
    if (idx < GG) counts[idx] = 0.f;
    if (idx < H2) { colsum[idx] = 0.f; colsq[idx] = 0.f; }
}

__global__ void copyz_kernel(const float* __restrict__ x, float* __restrict__ z) {
    size_t i = (size_t)blockIdx.x * blockDim.x + threadIdx.x;
    if (i < (size_t)NN * HH / 4) {
        reinterpret_cast<float4*>(z)[i] = reinterpret_cast<const float4*>(x)[i];
    }
}

// ---------------------------------------------------------------------------
// Edge scatter: 8 edges per warp, all gathers in flight before atomics
// ---------------------------------------------------------------------------
__global__ void scatter_kernel(const float* __restrict__ h, float* __restrict__ z,
                               const void* __restrict__ ei, int E,
                               const int* __restrict__ is64p) {
    int w = (int)(((size_t)blockIdx.x * blockDim.x + threadIdx.x) >> 5);
    int lane = threadIdx.x & 31;
    int Q = E >> 3;
    if (w >= Q) return;
    int is64 = *is64p;
    int src[8], dst[8];
#pragma unroll
    for (int e = 0; e < 8; e++) src[e] = load_index(ei, (size_t)(w + e * Q), is64);
#pragma unroll
    for (int e = 0; e < 8; e++) dst[e] = load_index(ei, (size_t)E + (w + e * Q), is64);
    float4 v[8];
#pragma unroll
    for (int e = 0; e < 8; e++)
        v[e] = *reinterpret_cast<const float4*>(&h[(size_t)src[e] * HH + lane * 4]);
#pragma unroll
    for (int e = 0; e < 8; e++)
        atomicAdd(reinterpret_cast<float4*>(&z[(size_t)dst[e] * HH + lane * 4]), v[e]);
}

// ---------------------------------------------------------------------------
// Tiled fp32 GEMM with fused BN-apply on A-load (TRANS) and fused BN column
// stats of the output (sum, sumsq -> global atomics).
// BM=BN=128, BK=16, 256 threads, 8x8 per thread, double-buffered smem,
// register-staged global prefetch, 1 sync per k-tile.
// ---------------------------------------------------------------------------
template <bool TRANS>
__global__ void __launch_bounds__(256, 2)
gemm_kernel(const float* __restrict__ A, const float* __restrict__ W,
            const float* __restrict__ bias, float* __restrict__ out,
            int M, int K, int CN,
            const float* __restrict__ tscale, const float* __restrict__ tshift,
            float* __restrict__ statsum, float* __restrict__ statsq) {
    __shared__ float As[2][16][128];   // [stage][k][m]
    __shared__ float Bs[2][16][128];   // [stage][k][n]
    __shared__ float s_scale[H2];
    __shared__ float s_shift[H2];

    int tid = threadIdx.x;
    int row0 = blockIdx.x * 128;
    int col0 = blockIdx.y * 128;
    int tx = tid & 15;
    int ty = tid >> 4;

    if (TRANS) {
        for (int i = tid; i < K; i += 256) {
            s_scale[i] = tscale[i];
            s_shift[i] = tshift[i];
        }
        __syncthreads();
    }

    int ar0 = tid >> 2;            // rows 0..63
    int ar1 = 64 + (tid >> 2);     // rows 64..127
    int aq = (tid & 3) * 4;        // k offset 0/4/8/12
    int bk0 = tid >> 5;            // 0..7
    int bk1 = 8 + (tid >> 5);      // 8..15
    int bc4 = (tid & 31) * 4;

    const int NK = K / 16;

    auto loadA = [&](int k0, int r) -> float4 {
        float4 v = make_float4(0.f, 0.f, 0.f, 0.f);
        int arow = row0 + r;
        if (arow < M) v = *reinterpret_cast<const float4*>(&A[(size_t)arow * K + k0 + aq]);
        if (TRANS) {
            int kk = k0 + aq;
            v.x = fmaxf(v.x * s_scale[kk + 0] + s_shift[kk + 0], 0.f);
            v.y = fmaxf(v.y * s_scale[kk + 1] + s_shift[kk + 1], 0.f);
            v.z = fmaxf(v.z * s_scale[kk + 2] + s_shift[kk + 2], 0.f);
            v.w = fmaxf(v.w * s_scale[kk + 3] + s_shift[kk + 3], 0.f);
        }
        return v;
    };

    float acc[8][8];
#pragma unroll
    for (int i = 0; i < 8; i++)
#pragma unroll
        for (int j = 0; j < 8; j++) acc[i][j] = 0.f;

    // prefetch tile 0
    float4 pa0 = loadA(0, ar0);
    float4 pa1 = loadA(0, ar1);
    float4 pb0 = *reinterpret_cast<const float4*>(&W[(size_t)bk0 * CN + col0 + bc4]);
    float4 pb1 = *reinterpret_cast<const float4*>(&W[(size_t)bk1 * CN + col0 + bc4]);
    {
        As[0][aq + 0][ar0] = pa0.x; As[0][aq + 1][ar0] = pa0.y;
        As[0][aq + 2][ar0] = pa0.z; As[0][aq + 3][ar0] = pa0.w;
        As[0][aq + 0][ar1] = pa1.x; As[0][aq + 1][ar1] = pa1.y;
        As[0][aq + 2][ar1] = pa1.z; As[0][aq + 3][ar1] = pa1.w;
        *reinterpret_cast<float4*>(&Bs[0][bk0][bc4]) = pb0;
        *reinterpret_cast<float4*>(&Bs[0][bk1][bc4]) = pb1;
    }
    __syncthreads();

    for (int kt = 0; kt < NK; kt++) {
        int cur = kt & 1;
        if (kt + 1 < NK) {
            int k0 = (kt + 1) * 16;
            pa0 = loadA(k0, ar0);
            pa1 = loadA(k0, ar1);
            pb0 = *reinterpret_cast<const float4*>(&W[(size_t)(k0 + bk0) * CN + col0 + bc4]);
            pb1 = *reinterpret_cast<const float4*>(&W[(size_t)(k0 + bk1) * CN + col0 + bc4]);
        }
#pragma unroll
        for (int k = 0; k < 16; k++) {
            float a[8], b[8];
            *reinterpret_cast<float4*>(&a[0]) = *reinterpret_cast<float4*>(&As[cur][k][ty * 8]);
            *reinterpret_cast<float4*>(&a[4]) = *reinterpret_cast<float4*>(&As[cur][k][ty * 8 + 4]);
            *reinterpret_cast<float4*>(&b[0]) = *reinterpret_cast<float4*>(&Bs[cur][k][tx * 8]);
            *reinterpret_cast<float4*>(&b[4]) = *reinterpret_cast<float4*>(&Bs[cur][k][tx * 8 + 4]);
#pragma unroll
            for (int i = 0; i < 8; i++)
#pragma unroll
                for (int j = 0; j < 8; j++)
                    acc[i][j] = fmaf(a[i], b[j], acc[i][j]);
        }
        if (kt + 1 < NK) {
            int nst = (kt + 1) & 1;
            As[nst][aq + 0][ar0] = pa0.x; As[nst][aq + 1][ar0] = pa0.y;
            As[nst][aq + 2][ar0] = pa0.z; As[nst][aq + 3][ar0] = pa0.w;
            As[nst][aq + 0][ar1] = pa1.x; As[nst][aq + 1][ar1] = pa1.y;
            As[nst][aq + 2][ar1] = pa1.z; As[nst][aq + 3][ar1] = pa1.w;
            *reinterpret_cast<float4*>(&Bs[nst][bk0][bc4]) = pb0;
            *reinterpret_cast<float4*>(&Bs[nst][bk1][bc4]) = pb1;
            __syncthreads();
        }
    }

    float bvals[8];
#pragma unroll
    for (int j = 0; j < 8; j++) bvals[j] = __ldg(&bias[col0 + tx * 8 + j]);

    // write output
#pragma unroll
    for (int i = 0; i < 8; i++) {
        int r = row0 + ty * 8 + i;
        if (r < M) {
            float4 o0, o1;
            o0.x = acc[i][0] + bvals[0]; o0.y = acc[i][1] + bvals[1];
            o0.z = acc[i][2] + bvals[2]; o0.w = acc[i][3] + bvals[3];
            o1.x = acc[i][4] + bvals[4]; o1.y = acc[i][5] + bvals[5];
            o1.z = acc[i][6] + bvals[6]; o1.w = acc[i][7] + bvals[7];
            *reinterpret_cast<float4*>(&out[(size_t)r * CN + col0 + tx * 8]) = o0;
            *reinterpret_cast<float4*>(&out[(size_t)r * CN + col0 + tx * 8 + 4]) = o1;
        }
    }

    // fused BN column stats of (acc + bias) over valid rows
    __syncthreads();                       // all smem reads done; reuse As
    float* red = &As[0][0][0];             // 16*128 floats
    float sv[8], qv[8];
#pragma unroll
    for (int j = 0; j < 8; j++) { sv[j] = 0.f; qv[j] = 0.f; }
#pragma unroll
    for (int i = 0; i < 8; i++) {
        int r = row0 + ty * 8 + i;
        if (r < M) {
#pragma unroll
            for (int j = 0; j < 8; j++) {
                float v = acc[i][j] + bvals[j];
                sv[j] += v;
                qv[j] += v * v;
            }
        }
    }
#pragma unroll
    for (int j = 0; j < 8; j++) red[ty * 128 + tx * 8 + j] = sv[j];
    __syncthreads();
    if (tid < 128) {
        float t = 0.f;
#pragma unroll
        for (int g = 0; g < 16; g++) t += red[g * 128 + tid];
        atomicAdd(&statsum[col0 + tid], t);
    }
    __syncthreads();
#pragma unroll
    for (int j = 0; j < 8; j++) red[ty * 128 + tx * 8 + j] = qv[j];
    __syncthreads();
    if (tid < 128) {
        float t = 0.f;
#pragma unroll
        for (int g = 0; g < 16; g++) t += red[g * 128 + tid];
        atomicAdd(&statsq[col0 + tid], t);
    }
}

// ---------------------------------------------------------------------------
// Column stats for the tiny virtual-node tensors
// ---------------------------------------------------------------------------
template <int C>
__global__ void colstats_kernel(const float* __restrict__ X, int Nrows,
                                float* __restrict__ sum, float* __restrict__ sq) {
    int c = threadIdx.x;
    float s = 0.f, q = 0.f;
    for (int r = blockIdx.x; r < Nrows; r += gridDim.x) {
        float v = X[(size_t)r * C + c];
        s += v;
        q += v * v;
    }
    atomicAdd(&sum[c], s);
    atomicAdd(&sq[c], q);
}

__global__ void bn_finalize_kernel(float* __restrict__ sum, float* __restrict__ sq,
                                   const float* __restrict__ g, const float* __restrict__ b,
                                   float* __restrict__ scale, float* __restrict__ shift,
                                   int C, float invN) {
    int c = threadIdx.x;
    if (c < C) {
        float m = sum[c] * invN;
        float v = sq[c] * invN - m * m;
        float sc = __ldg(&g[c]) * rsqrtf(v + BN_EPS);
        scale[c] = sc;
        shift[c] = __ldg(&b[c]) - m * sc;
        sum[c] = 0.f;
        sq[c] = 0.f;
    }
}

// ---------------------------------------------------------------------------
// Per-layer finalize / prep kernels
// ---------------------------------------------------------------------------
__global__ void prep0_kernel(const float* __restrict__ u, const float* __restrict__ sc,
                             const float* __restrict__ sh, const float* __restrict__ vn_emb,
                             float* __restrict__ h, float* __restrict__ z) {
    size_t idx = (size_t)blockIdx.x * blockDim.x + threadIdx.x;
    if (idx >= (size_t)NN * (HH / 4)) return;
    int c = (int)(idx & 31) * 4;
    float4 v = reinterpret_cast<const float4*>(u)[idx];
    float4 r;
    r.x = fmaxf(v.x * sc[c + 0] + sh[c + 0], 0.f) + __ldg(&vn_emb[c + 0]);
    r.y = fmaxf(v.y * sc[c + 1] + sh[c + 1], 0.f) + __ldg(&vn_emb[c + 1]);
    r.z = fmaxf(v.z * sc[c + 2] + sh[c + 2], 0.f) + __ldg(&vn_emb[c + 2]);
    r.w = fmaxf(v.w * sc[c + 3] + sh[c + 3], 0.f) + __ldg(&vn_emb[c + 3]);
    reinterpret_cast<float4*>(h)[idx] = r;
    reinterpret_cast<float4*>(z)[idx] = r;
}

__global__ void fin1_kernel(const float* __restrict__ u, const float* __restrict__ sc,
                            const float* __restrict__ sh, float* __restrict__ f,
                            const void* __restrict__ batch, float* __restrict__ pooled,
                            const int* __restrict__ is64p) {
    size_t idx = (size_t)blockIdx.x * blockDim.x + threadIdx.x;
    if (idx >= (size_t)NN * (HH / 4)) return;
    int n = (int)(idx >> 5);
    int c = (int)(idx & 31) * 4;
    float4 v = reinterpret_cast<const float4*>(u)[idx];
    float4 r;
    r.x = fmaxf(v.x * sc[c + 0] + sh[c + 0], 0.f);
    r.y = fmaxf(v.y * sc[c + 1] + sh[c + 1], 0.f);
    r.z = fmaxf(v.z * sc[c + 2] + sh[c + 2], 0.f);
    r.w = fmaxf(v.w * sc[c + 3] + sh[c + 3], 0.f);
    reinterpret_cast<float4*>(f)[idx] = r;
    int g = load_index(batch, n, *is64p);
    atomicAdd(reinterpret_cast<float4*>(&pooled[(size_t)g * HH + c]), r);
}

__global__ void prep1_kernel(const float* __restrict__ f, const float* __restrict__ vf,
                             const void* __restrict__ batch,
                             float* __restrict__ h, float* __restrict__ z,
                             const int* __restrict__ is64p) {
    size_t idx = (size_t)blockIdx.x * blockDim.x + threadIdx.x;
    if (idx >= (size_t)NN * (HH / 4)) return;
    int n = (int)(idx >> 5);
    int c = (int)(idx & 31) * 4;
    int g = load_index(batch, n, *is64p);
    float4 a = reinterpret_cast<const float4*>(f)[idx];
    float4 b = *reinterpret_cast<const float4*>(&vf[(size_t)g * HH + c]);
    float4 r;
    r.x = a.x + b.x; r.y = a.y + b.y; r.z = a.z + b.z; r.w = a.w + b.w;
    reinterpret_cast<float4*>(h)[idx] = r;
    reinterpret_cast<float4*>(z)[idx] = r;
}

__global__ void fin2_kernel(const float* __restrict__ u, const float* __restrict__ sc,
                            const float* __restrict__ sh, float* __restrict__ out_feats,
                            const void* __restrict__ batch,
                            float* __restrict__ readout, float* __restrict__ counts,
                            const int* __restrict__ is64p) {
    size_t idx = (size_t)blockIdx.x * blockDim.x + threadIdx.x;
    if (idx >= (size_t)NN * (HH / 4)) return;
    int n = (int)(idx >> 5);
    int c = (int)(idx & 31) * 4;
    float4 v = reinterpret_cast<const float4*>(u)[idx];
    float4 r;
    r.x = v.x * sc[c + 0] + sh[c + 0];
    r.y = v.y * sc[c + 1] + sh[c + 1];
    r.z = v.z * sc[c + 2] + sh[c + 2];
    r.w = v.w * sc[c + 3] + sh[c + 3];
    reinterpret_cast<float4*>(out_feats)[idx] = r;
    int g = load_index(batch, n, *is64p);
    atomicAdd(reinterpret_cast<float4*>(&readout[(size_t)g * HH + c]), r);
    if (c == 0) atomicAdd(&counts[g], 1.0f);
}

__global__ void epilogue_kernel(float* __restrict__ readout, const float* __restrict__ counts,
                                const float* __restrict__ vf, float* __restrict__ vf_out) {
    int idx = blockIdx.x * blockDim.x + threadIdx.x;
    if (idx < GG * HH) {
        float cnt = fmaxf(counts[idx >> 7], 1.0f);
        readout[idx] = readout[idx] / cnt;
        vf_out[idx] = vf[idx];
    }
}

// ---------------------------------------------------------------------------
// Virtual-node MLP kernels (tiny: G=512 rows)
// ---------------------------------------------------------------------------
__global__ void vgemm1_kernel(const float* __restrict__ pooled, const float* __restrict__ vf,
                              const float* __restrict__ W, const float* __restrict__ b,
                              float* __restrict__ out) {
    int g = blockIdx.x;
    int c = threadIdx.x;
    __shared__ float a[HH];
    if (c < HH) a[c] = pooled[g * HH + c] + vf[g * HH + c];
    __syncthreads();
    float acc = __ldg(&b[c]);
#pragma unroll 8
    for (int k = 0; k < HH; k++) acc = fmaf(a[k], __ldg(&W[k * H2 + c]), acc);
    out[g * H2 + c] = acc;
}

__global__ void vgemm2_kernel(const float* __restrict__ vt2, const float* __restrict__ vs,
                              const float* __restrict__ vsh, const float* __restrict__ W,
                              const float* __restrict__ b, float* __restrict__ out) {
    int g = blockIdx.x;
    int c = threadIdx.x;
    __shared__ float a[H2];
    for (int k = c; k < H2; k += HH)
        a[k] = fmaxf(vt2[g * H2 + k] * vs[k] + vsh[k], 0.f);
    __syncthreads();
    float acc = __ldg(&b[c]);
#pragma unroll 8
    for (int k = 0; k < H2; k++) acc = fmaf(a[k], __ldg(&W[k * HH + c]), acc);
    out[g * HH + c] = acc;
}

__global__ void vapply_kernel(const float* __restrict__ vt1, const float* __restrict__ vs,
                              const float* __restrict__ vsh, float* __restrict__ vf) {
    int idx = blockIdx.x * blockDim.x + threadIdx.x;
    if (idx < GG * HH) {
        int c = idx & (HH - 1);
        vf[idx] = fmaxf(vt1[idx] * vs[c] + vsh[c], 0.f);
    }
}

// ---------------------------------------------------------------------------
// Host driver
// ---------------------------------------------------------------------------
extern "C" void kernel_launch(void* const* d_in, const int* in_sizes, int n_in,
                              void* d_out, int out_size) {
    int off = (n_in > 3 && in_sizes[3] <= 4) ? 1 : 0;
    const float* x            = (const float*)d_in[0];
    const void*  ei           = d_in[1];
    const void*  batch        = d_in[2];
    const float* conv_w1      = (const float*)d_in[3 + off];
    const float* conv_b1      = (const float*)d_in[4 + off];
    const float* conv_bn_g    = (const float*)d_in[5 + off];
    const float* conv_bn_b    = (const float*)d_in[6 + off];
    const float* conv_w2      = (const float*)d_in[7 + off];
    const float* conv_b2      = (const float*)d_in[8 + off];
    const float* bn_g         = (const float*)d_in[9 + off];
    const float* bn_b         = (const float*)d_in[10 + off];
    const float* vn_emb       = (const float*)d_in[11 + off];
    const float* vmlp_w1      = (const float*)d_in[12 + off];
    const float* vmlp_b1      = (const float*)d_in[13 + off];
    const float* vmlp_bn1_g   = (const float*)d_in[14 + off];
    const float* vmlp_bn1_b   = (const float*)d_in[15 + off];
    const float* vmlp_w2      = (const float*)d_in[16 + off];
    const float* vmlp_b2      = (const float*)d_in[17 + off];
    const float* vmlp_bn2_g   = (const float*)d_in[18 + off];
    const float* vmlp_bn2_b   = (const float*)d_in[19 + off];

    float* out = (float*)d_out;
    float* out_feats = out;
    float* out_readout = out + (size_t)NN * HH;
    float* out_vf = out_readout + GG * HH;

    float *p_z, *p_h, *p_t, *p_u, *p_f, *p_colsum, *p_colsq, *p_scaleA, *p_shiftA,
          *p_scaleB, *p_shiftB, *p_vf, *p_pooled, *p_vt2, *p_vt1, *p_counts,
          *p_vscale, *p_vshift;
    int* p_is64;
    cudaGetSymbolAddress((void**)&p_z, g_z);
    cudaGetSymbolAddress((void**)&p_h, g_h);
    cudaGetSymbolAddress((void**)&p_t, g_t);
    cudaGetSymbolAddress((void**)&p_u, g_u);
    cudaGetSymbolAddress((void**)&p_f, g_f);
    cudaGetSymbolAddress((void**)&p_colsum, g_colsum);
    cudaGetSymbolAddress((void**)&p_colsq, g_colsq);
    cudaGetSymbolAddress((void**)&p_scaleA, g_scaleA);
    cudaGetSymbolAddress((void**)&p_shiftA, g_shiftA);
    cudaGetSymbolAddress((void**)&p_scaleB, g_scaleB);
    cudaGetSymbolAddress((void**)&p_shiftB, g_shiftB);
    cudaGetSymbolAddress((void**)&p_vf, g_vf);
    cudaGetSymbolAddress((void**)&p_pooled, g_pooled);
    cudaGetSymbolAddress((void**)&p_vt2, g_vt2);
    cudaGetSymbolAddress((void**)&p_vt1, g_vt1);
    cudaGetSymbolAddress((void**)&p_counts, g_counts);
    cudaGetSymbolAddress((void**)&p_vscale, g_vscale);
    cudaGetSymbolAddress((void**)&p_vshift, g_vshift);
    cudaGetSymbolAddress((void**)&p_is64, g_is64);

    const int M = NN;
    const float invN = 1.0f / (float)NN;
    const float invG = 1.0f / (float)GG;
    dim3 gemm_grid1((M + 127) / 128, H2 / 128);
    dim3 gemm_grid2((M + 127) / 128, HH / 128);
    int ew_blocks = (NN * (HH / 4) + 255) / 256;
    int sc_blocks = ((EE / 8) + 7) / 8;     // 8 edges per warp, 8 warps/block

    detect_kernel<<<1, 1024>>>((const int*)ei, p_is64);
    init_kernel<<<(GG * HH + 255) / 256, 256>>>(vn_emb, out_readout, p_vf, p_pooled,
                                                p_counts, p_colsum, p_colsq);
    copyz_kernel<<<(NN * HH / 4 + 255) / 256, 256>>>(x, p_z);

    for (int l = 0; l < LL; l++) {
        const float* w1 = conv_w1 + (size_t)l * HH * H2;
        const float* b1 = conv_b1 + l * H2;
        const float* cg = conv_bn_g + l * H2;
        const float* cb = conv_bn_b + l * H2;
        const float* w2 = conv_w2 + (size_t)l * H2 * HH;
        const float* b2 = conv_b2 + l * HH;
        const float* og = bn_g + l * HH;
        const float* ob = bn_b + l * HH;

        const float* hsrc = (l == 0) ? x : p_h;
        scatter_kernel<<<sc_blocks, 256>>>(hsrc, p_z, ei, EE, p_is64);

        // GEMM1 (+fused stats) -> finalize
        gemm_kernel<false><<<gemm_grid1, 256>>>(p_z, w1, b1, p_t, M, HH, H2,
                                                nullptr, nullptr, p_colsum, p_colsq);
        bn_finalize_kernel<<<1, 256>>>(p_colsum, p_colsq, cg, cb, p_scaleA, p_shiftA,
                                       H2, invN);

        // GEMM2 with fused BN+ReLU on A-load (+fused stats) -> finalize
        gemm_kernel<true><<<gemm_grid2, 256>>>(p_t, w2, b2, p_u, M, H2, HH,
                                               p_scaleA, p_shiftA, p_colsum, p_colsq);
        bn_finalize_kernel<<<1, 256>>>(p_colsum, p_colsq, og, ob, p_scaleB, p_shiftB,
                                       HH, invN);

        if (l == 0) {
            prep0_kernel<<<ew_blocks, 256>>>(p_u, p_scaleB, p_shiftB, vn_emb, p_h, p_z);
        } else if (l == 1) {
            fin1_kernel<<<ew_blocks, 256>>>(p_u, p_scaleB, p_shiftB, p_f, batch, p_pooled,
                                            p_is64);
            vgemm1_kernel<<<GG, H2>>>(p_pooled, p_vf, vmlp_w1, vmlp_b1, p_vt2);
            colstats_kernel<H2><<<64, H2>>>(p_vt2, GG, p_colsum, p_colsq);
            bn_finalize_kernel<<<1, 256>>>(p_colsum, p_colsq, vmlp_bn1_g, vmlp_bn1_b,
                                           p_vscale, p_vshift, H2, invG);
            vgemm2_kernel<<<GG, HH>>>(p_vt2, p_vscale, p_vshift, vmlp_w2, vmlp_b2, p_vt1);
            colstats_kernel<HH><<<64, HH>>>(p_vt1, GG, p_colsum, p_colsq);
            bn_finalize_kernel<<<1, 256>>>(p_colsum, p_colsq, vmlp_bn2_g, vmlp_bn2_b,
                                           p_vscale, p_vshift, HH, invG);
            vapply_kernel<<<(GG * HH + 255) / 256, 256>>>(p_vt1, p_vscale, p_vshift, p_vf);
            prep1_kernel<<<ew_blocks, 256>>>(p_f, p_vf, batch, p_h, p_z, p_is64);
        } else {
            fin2_kernel<<<ew_blocks, 256>>>(p_u, p_scaleB, p_shiftB, out_feats, batch,
                                            out_readout, p_counts, p_is64);
        }
    }

    epilogue_kernel<<<(GG * HH + 255) / 256, 256>>>(out_readout, p_counts, p_vf, out_vf);
    (void)in_sizes; (void)n_in; (void)out_size;
}

// round 12
// speedup vs baseline: 1.3160x; 1.0775x over previous
#include <cuda_runtime.h>
#include <cstdint>

// ---------------------------------------------------------------------------
// Problem constants
// ---------------------------------------------------------------------------
#define NN 100000
#define EE 1600000
#define HH 128
#define H2 256
#define GG 512
#define LL 3
#define BN_EPS 1e-5f

// ---------------------------------------------------------------------------
// Scratch (device globals; no dynamic allocation allowed)
// ---------------------------------------------------------------------------
__device__ float g_z[(size_t)NN * HH];
__device__ float g_h[(size_t)NN * HH];
__device__ float g_t[(size_t)NN * H2];
__device__ float g_u[(size_t)NN * HH];
__device__ float g_f[(size_t)NN * HH];
__device__ float g_colsum[H2];
__device__ float g_colsq[H2];
__device__ float g_scaleA[H2];
__device__ float g_shiftA[H2];
__device__ float g_scaleB[HH];
__device__ float g_shiftB[HH];
__device__ float g_vf[GG * HH];
__device__ float g_pooled[GG * HH];
__device__ float g_vt2[GG * H2];
__device__ float g_vt1[GG * HH];
__device__ float g_counts[GG];
__device__ float g_vscale[H2];
__device__ float g_vshift[H2];
__device__ int   g_is64;

// ---------------------------------------------------------------------------
// Packed f32x2 helpers (PTX: sm_100+ base ISA)
// ---------------------------------------------------------------------------
__device__ __forceinline__ unsigned long long f2pack(float lo, float hi) {
    unsigned long long r;
    asm("mov.b64 %0, {%1, %2};" : "=l"(r) : "f"(lo), "f"(hi));
    return r;
}
__device__ __forceinline__ void f2unpack(unsigned long long v, float& lo, float& hi) {
    asm("mov.b64 {%0, %1}, %2;" : "=f"(lo), "=f"(hi) : "l"(v));
}
__device__ __forceinline__ void fma2(unsigned long long& d, unsigned long long a,
                                     unsigned long long b) {
    asm("fma.rn.f32x2 %0, %1, %2, %0;" : "+l"(d) : "l"(a), "l"(b));
}

// ---------------------------------------------------------------------------
// dtype detect: int64 nonneg values < 2^31 have zero high (odd) 32-bit words.
// ---------------------------------------------------------------------------
__global__ void detect_kernel(const int* __restrict__ ei32, int* __restrict__ flag) {
    __shared__ int any;
    if (threadIdx.x == 0) any = 0;
    __syncthreads();
    int v = ei32[2 * threadIdx.x + 1];
    if (v != 0) atomicOr(&any, 1);
    __syncthreads();
    if (threadIdx.x == 0) *flag = any ? 0 : 1;
}

__device__ __forceinline__ int load_index(const void* __restrict__ p, size_t i, int is64) {
    if (is64) return (int)reinterpret_cast<const long long*>(p)[i];
    return reinterpret_cast<const int*>(p)[i];
}

// ---------------------------------------------------------------------------
// init
// ---------------------------------------------------------------------------
__global__ void init_kernel(const float* __restrict__ vn_emb,
                            float* __restrict__ out_readout,
                            float* __restrict__ vf, float* __restrict__ pooled,
                            float* __restrict__ counts,
                            float* __restrict__ colsum, float* __restrict__ colsq) {
    int idx = blockIdx.x * blockDim.x + threadIdx.x;
    if (idx < GG * HH) {
        pooled[idx] = 0.f;
        out_readout[idx] = 0.f;
        vf[idx] = __ldg(&vn_emb[idx & (HH - 1)]);
    }
    if (idx < GG) counts[idx] = 0.f;
    if (idx < H2) { colsum[idx] = 0.f; colsq[idx] = 0.f; }
}

__global__ void copyz_kernel(const float* __restrict__ x, float* __restrict__ z) {
    size_t i = (size_t)blockIdx.x * blockDim.x + threadIdx.x;
    if (i < (size_t)NN * HH / 4) {
        reinterpret_cast<float4*>(z)[i] = reinterpret_cast<const float4*>(x)[i];
    }
}

// ---------------------------------------------------------------------------
// Edge scatter: 8 edges per warp, all gathers in flight before atomics
// ---------------------------------------------------------------------------
__global__ void scatter_kernel(const float* __restrict__ h, float* __restrict__ z,
                               const void* __restrict__ ei, int E,
                               const int* __restrict__ is64p) {
    int w = (int)(((size_t)blockIdx.x * blockDim.x + threadIdx.x) >> 5);
    int lane = threadIdx.x & 31;
    int Q = E >> 3;
    if (w >= Q) return;
    int is64 = *is64p;
    int src[8], dst[8];
#pragma unroll
    for (int e = 0; e < 8; e++) src[e] = load_index(ei, (size_t)(w + e * Q), is64);
#pragma unroll
    for (int e = 0; e < 8; e++) dst[e] = load_index(ei, (size_t)E + (w + e * Q), is64);
    float4 v[8];
#pragma unroll
    for (int e = 0; e < 8; e++)
        v[e] = *reinterpret_cast<const float4*>(&h[(size_t)src[e] * HH + lane * 4]);
#pragma unroll
    for (int e = 0; e < 8; e++)
        atomicAdd(reinterpret_cast<float4*>(&z[(size_t)dst[e] * HH + lane * 4]), v[e]);
}

// ---------------------------------------------------------------------------
// Tiled fp32 GEMM using packed fma.rn.f32x2 (2 FMAs/inst), fused BN-apply on
// A-load (TRANS) and fused BN column stats of the output.
// BM=BN=128, BK=16, 256 threads, 8x8 per thread (4x8 packed row-pair accs),
// double-buffered smem, register-staged prefetch, 1 sync per k-tile.
// ---------------------------------------------------------------------------
template <bool TRANS>
__global__ void __launch_bounds__(256, 2)
gemm_kernel(const float* __restrict__ A, const float* __restrict__ W,
            const float* __restrict__ bias, float* __restrict__ out,
            int M, int K, int CN,
            const float* __restrict__ tscale, const float* __restrict__ tshift,
            float* __restrict__ statsum, float* __restrict__ statsq) {
    __shared__ float As[2][16][128];   // [stage][k][m]
    __shared__ float Bs[2][16][128];   // [stage][k][n]
    __shared__ float s_scale[H2];
    __shared__ float s_shift[H2];

    int tid = threadIdx.x;
    int row0 = blockIdx.x * 128;
    int col0 = blockIdx.y * 128;
    int tx = tid & 15;
    int ty = tid >> 4;

    if (TRANS) {
        for (int i = tid; i < K; i += 256) {
            s_scale[i] = tscale[i];
            s_shift[i] = tshift[i];
        }
        __syncthreads();
    }

    int ar0 = tid >> 2;            // rows 0..63
    int ar1 = 64 + (tid >> 2);     // rows 64..127
    int aq = (tid & 3) * 4;        // k offset 0/4/8/12
    int bk0 = tid >> 5;            // 0..7
    int bk1 = 8 + (tid >> 5);      // 8..15
    int bc4 = (tid & 31) * 4;

    const int NK = K / 16;

    auto loadA = [&](int k0, int r) -> float4 {
        float4 v = make_float4(0.f, 0.f, 0.f, 0.f);
        int arow = row0 + r;
        if (arow < M) v = *reinterpret_cast<const float4*>(&A[(size_t)arow * K + k0 + aq]);
        if (TRANS) {
            int kk = k0 + aq;
            v.x = fmaxf(v.x * s_scale[kk + 0] + s_shift[kk + 0], 0.f);
            v.y = fmaxf(v.y * s_scale[kk + 1] + s_shift[kk + 1], 0.f);
            v.z = fmaxf(v.z * s_scale[kk + 2] + s_shift[kk + 2], 0.f);
            v.w = fmaxf(v.w * s_scale[kk + 3] + s_shift[kk + 3], 0.f);
        }
        return v;
    };

    // packed accumulators: acc2[ip][j] = {acc[2ip][j], acc[2ip+1][j]}
    unsigned long long acc2[4][8];
    const unsigned long long zz = f2pack(0.f, 0.f);
#pragma unroll
    for (int ip = 0; ip < 4; ip++)
#pragma unroll
        for (int j = 0; j < 8; j++) acc2[ip][j] = zz;

    // prefetch tile 0
    float4 pa0 = loadA(0, ar0);
    float4 pa1 = loadA(0, ar1);
    float4 pb0 = *reinterpret_cast<const float4*>(&W[(size_t)bk0 * CN + col0 + bc4]);
    float4 pb1 = *reinterpret_cast<const float4*>(&W[(size_t)bk1 * CN + col0 + bc4]);
    {
        As[0][aq + 0][ar0] = pa0.x; As[0][aq + 1][ar0] = pa0.y;
        As[0][aq + 2][ar0] = pa0.z; As[0][aq + 3][ar0] = pa0.w;
        As[0][aq + 0][ar1] = pa1.x; As[0][aq + 1][ar1] = pa1.y;
        As[0][aq + 2][ar1] = pa1.z; As[0][aq + 3][ar1] = pa1.w;
        *reinterpret_cast<float4*>(&Bs[0][bk0][bc4]) = pb0;
        *reinterpret_cast<float4*>(&Bs[0][bk1][bc4]) = pb1;
    }
    __syncthreads();

    for (int kt = 0; kt < NK; kt++) {
        int cur = kt & 1;
        if (kt + 1 < NK) {
            int k0 = (kt + 1) * 16;
            pa0 = loadA(k0, ar0);
            pa1 = loadA(k0, ar1);
            pb0 = *reinterpret_cast<const float4*>(&W[(size_t)(k0 + bk0) * CN + col0 + bc4]);
            pb1 = *reinterpret_cast<const float4*>(&W[(size_t)(k0 + bk1) * CN + col0 + bc4]);
        }
#pragma unroll
        for (int k = 0; k < 16; k++) {
            float a[8], b[8];
            *reinterpret_cast<float4*>(&a[0]) = *reinterpret_cast<float4*>(&As[cur][k][ty * 8]);
            *reinterpret_cast<float4*>(&a[4]) = *reinterpret_cast<float4*>(&As[cur][k][ty * 8 + 4]);
            *reinterpret_cast<float4*>(&b[0]) = *reinterpret_cast<float4*>(&Bs[cur][k][tx * 8]);
            *reinterpret_cast<float4*>(&b[4]) = *reinterpret_cast<float4*>(&Bs[cur][k][tx * 8 + 4]);
            unsigned long long ap[4], br[8];
#pragma unroll
            for (int ip = 0; ip < 4; ip++) ap[ip] = f2pack(a[2 * ip], a[2 * ip + 1]);
#pragma unroll
            for (int j = 0; j < 8; j++) br[j] = f2pack(b[j], b[j]);
#pragma unroll
            for (int ip = 0; ip < 4; ip++)
#pragma unroll
                for (int j = 0; j < 8; j++)
                    fma2(acc2[ip][j], ap[ip], br[j]);
        }
        if (kt + 1 < NK) {
            int nst = (kt + 1) & 1;
            As[nst][aq + 0][ar0] = pa0.x; As[nst][aq + 1][ar0] = pa0.y;
            As[nst][aq + 2][ar0] = pa0.z; As[nst][aq + 3][ar0] = pa0.w;
            As[nst][aq + 0][ar1] = pa1.x; As[nst][aq + 1][ar1] = pa1.y;
            As[nst][aq + 2][ar1] = pa1.z; As[nst][aq + 3][ar1] = pa1.w;
            *reinterpret_cast<float4*>(&Bs[nst][bk0][bc4]) = pb0;
            *reinterpret_cast<float4*>(&Bs[nst][bk1][bc4]) = pb1;
            __syncthreads();
        }
    }

    // unpack accumulators
    float acc[8][8];
#pragma unroll
    for (int ip = 0; ip < 4; ip++)
#pragma unroll
        for (int j = 0; j < 8; j++)
            f2unpack(acc2[ip][j], acc[2 * ip][j], acc[2 * ip + 1][j]);

    float bvals[8];
#pragma unroll
    for (int j = 0; j < 8; j++) bvals[j] = __ldg(&bias[col0 + tx * 8 + j]);

    // write output
#pragma unroll
    for (int i = 0; i < 8; i++) {
        int r = row0 + ty * 8 + i;
        if (r < M) {
            float4 o0, o1;
            o0.x = acc[i][0] + bvals[0]; o0.y = acc[i][1] + bvals[1];
            o0.z = acc[i][2] + bvals[2]; o0.w = acc[i][3] + bvals[3];
            o1.x = acc[i][4] + bvals[4]; o1.y = acc[i][5] + bvals[5];
            o1.z = acc[i][6] + bvals[6]; o1.w = acc[i][7] + bvals[7];
            *reinterpret_cast<float4*>(&out[(size_t)r * CN + col0 + tx * 8]) = o0;
            *reinterpret_cast<float4*>(&out[(size_t)r * CN + col0 + tx * 8 + 4]) = o1;
        }
    }

    // fused BN column stats of (acc + bias) over valid rows
    __syncthreads();                       // all smem reads done; reuse As
    float* red = &As[0][0][0];             // 16*128 floats
    float sv[8], qv[8];
#pragma unroll
    for (int j = 0; j < 8; j++) { sv[j] = 0.f; qv[j] = 0.f; }
#pragma unroll
    for (int i = 0; i < 8; i++) {
        int r = row0 + ty * 8 + i;
        if (r < M) {
#pragma unroll
            for (int j = 0; j < 8; j++) {
                float v = acc[i][j] + bvals[j];
                sv[j] += v;
                qv[j] += v * v;
            }
        }
    }
#pragma unroll
    for (int j = 0; j < 8; j++) red[ty * 128 + tx * 8 + j] = sv[j];
    __syncthreads();
    if (tid < 128) {
        float t = 0.f;
#pragma unroll
        for (int g = 0; g < 16; g++) t += red[g * 128 + tid];
        atomicAdd(&statsum[col0 + tid], t);
    }
    __syncthreads();
#pragma unroll
    for (int j = 0; j < 8; j++) red[ty * 128 + tx * 8 + j] = qv[j];
    __syncthreads();
    if (tid < 128) {
        float t = 0.f;
#pragma unroll
        for (int g = 0; g < 16; g++) t += red[g * 128 + tid];
        atomicAdd(&statsq[col0 + tid], t);
    }
}

// ---------------------------------------------------------------------------
// Column stats for the tiny virtual-node tensors
// ---------------------------------------------------------------------------
template <int C>
__global__ void colstats_kernel(const float* __restrict__ X, int Nrows,
                                float* __restrict__ sum, float* __restrict__ sq) {
    int c = threadIdx.x;
    float s = 0.f, q = 0.f;
    for (int r = blockIdx.x; r < Nrows; r += gridDim.x) {
        float v = X[(size_t)r * C + c];
        s += v;
        q += v * v;
    }
    atomicAdd(&sum[c], s);
    atomicAdd(&sq[c], q);
}

__global__ void bn_finalize_kernel(float* __restrict__ sum, float* __restrict__ sq,
                                   const float* __restrict__ g, const float* __restrict__ b,
                                   float* __restrict__ scale, float* __restrict__ shift,
                                   int C, float invN) {
    int c = threadIdx.x;
    if (c < C) {
        float m = sum[c] * invN;
        float v = sq[c] * invN - m * m;
        float sc = __ldg(&g[c]) * rsqrtf(v + BN_EPS);
        scale[c] = sc;
        shift[c] = __ldg(&b[c]) - m * sc;
        sum[c] = 0.f;
        sq[c] = 0.f;
    }
}

// ---------------------------------------------------------------------------
// Per-layer finalize / prep kernels
// ---------------------------------------------------------------------------
__global__ void prep0_kernel(const float* __restrict__ u, const float* __restrict__ sc,
                             const float* __restrict__ sh, const float* __restrict__ vn_emb,
                             float* __restrict__ h, float* __restrict__ z) {
    size_t idx = (size_t)blockIdx.x * blockDim.x + threadIdx.x;
    if (idx >= (size_t)NN * (HH / 4)) return;
    int c = (int)(idx & 31) * 4;
    float4 v = reinterpret_cast<const float4*>(u)[idx];
    float4 r;
    r.x = fmaxf(v.x * sc[c + 0] + sh[c + 0], 0.f) + __ldg(&vn_emb[c + 0]);
    r.y = fmaxf(v.y * sc[c + 1] + sh[c + 1], 0.f) + __ldg(&vn_emb[c + 1]);
    r.z = fmaxf(v.z * sc[c + 2] + sh[c + 2], 0.f) + __ldg(&vn_emb[c + 2]);
    r.w = fmaxf(v.w * sc[c + 3] + sh[c + 3], 0.f) + __ldg(&vn_emb[c + 3]);
    reinterpret_cast<float4*>(h)[idx] = r;
    reinterpret_cast<float4*>(z)[idx] = r;
}

__global__ void fin1_kernel(const float* __restrict__ u, const float* __restrict__ sc,
                            const float* __restrict__ sh, float* __restrict__ f,
                            const void* __restrict__ batch, float* __restrict__ pooled,
                            const int* __restrict__ is64p) {
    size_t idx = (size_t)blockIdx.x * blockDim.x + threadIdx.x;
    if (idx >= (size_t)NN * (HH / 4)) return;
    int n = (int)(idx >> 5);
    int c = (int)(idx & 31) * 4;
    float4 v = reinterpret_cast<const float4*>(u)[idx];
    float4 r;
    r.x = fmaxf(v.x * sc[c + 0] + sh[c + 0], 0.f);
    r.y = fmaxf(v.y * sc[c + 1] + sh[c + 1], 0.f);
    r.z = fmaxf(v.z * sc[c + 2] + sh[c + 2], 0.f);
    r.w = fmaxf(v.w * sc[c + 3] + sh[c + 3], 0.f);
    reinterpret_cast<float4*>(f)[idx] = r;
    int g = load_index(batch, n, *is64p);
    atomicAdd(reinterpret_cast<float4*>(&pooled[(size_t)g * HH + c]), r);
}

__global__ void prep1_kernel(const float* __restrict__ f, const float* __restrict__ vf,
                             const void* __restrict__ batch,
                             float* __restrict__ h, float* __restrict__ z,
                             const int* __restrict__ is64p) {
    size_t idx = (size_t)blockIdx.x * blockDim.x + threadIdx.x;
    if (idx >= (size_t)NN * (HH / 4)) return;
    int n = (int)(idx >> 5);
    int c = (int)(idx & 31) * 4;
    int g = load_index(batch, n, *is64p);
    float4 a = reinterpret_cast<const float4*>(f)[idx];
    float4 b = *reinterpret_cast<const float4*>(&vf[(size_t)g * HH + c]);
    float4 r;
    r.x = a.x + b.x; r.y = a.y + b.y; r.z = a.z + b.z; r.w = a.w + b.w;
    reinterpret_cast<float4*>(h)[idx] = r;
    reinterpret_cast<float4*>(z)[idx] = r;
}

__global__ void fin2_kernel(const float* __restrict__ u, const float* __restrict__ sc,
                            const float* __restrict__ sh, float* __restrict__ out_feats,
                            const void* __restrict__ batch,
                            float* __restrict__ readout, float* __restrict__ counts,
                            const int* __restrict__ is64p) {
    size_t idx = (size_t)blockIdx.x * blockDim.x + threadIdx.x;
    if (idx >= (size_t)NN * (HH / 4)) return;
    int n = (int)(idx >> 5);
    int c = (int)(idx & 31) * 4;
    float4 v = reinterpret_cast<const float4*>(u)[idx];
    float4 r;
    r.x = v.x * sc[c + 0] + sh[c + 0];
    r.y = v.y * sc[c + 1] + sh[c + 1];
    r.z = v.z * sc[c + 2] + sh[c + 2];
    r.w = v.w * sc[c + 3] + sh[c + 3];
    reinterpret_cast<float4*>(out_feats)[idx] = r;
    int g = load_index(batch, n, *is64p);
    atomicAdd(reinterpret_cast<float4*>(&readout[(size_t)g * HH + c]), r);
    if (c == 0) atomicAdd(&counts[g], 1.0f);
}

__global__ void epilogue_kernel(float* __restrict__ readout, const float* __restrict__ counts,
                                const float* __restrict__ vf, float* __restrict__ vf_out) {
    int idx = blockIdx.x * blockDim.x + threadIdx.x;
    if (idx < GG * HH) {
        float cnt = fmaxf(counts[idx >> 7], 1.0f);
        readout[idx] = readout[idx] / cnt;
        vf_out[idx] = vf[idx];
    }
}

// ---------------------------------------------------------------------------
// Virtual-node MLP kernels (tiny: G=512 rows)
// ---------------------------------------------------------------------------
__global__ void vgemm1_kernel(const float* __restrict__ pooled, const float* __restrict__ vf,
                              const float* __restrict__ W, const float* __restrict__ b,
                              float* __restrict__ out) {
    int g = blockIdx.x;
    int c = threadIdx.x;
    __shared__ float a[HH];
    if (c < HH) a[c] = pooled[g * HH + c] + vf[g * HH + c];
    __syncthreads();
    float acc = __ldg(&b[c]);
#pragma unroll 8
    for (int k = 0; k < HH; k++) acc = fmaf(a[k], __ldg(&W[k * H2 + c]), acc);
    out[g * H2 + c] = acc;
}

__global__ void vgemm2_kernel(const float* __restrict__ vt2, const float* __restrict__ vs,
                              const float* __restrict__ vsh, const float* __restrict__ W,
                              const float* __restrict__ b, float* __restrict__ out) {
    int g = blockIdx.x;
    int c = threadIdx.x;
    __shared__ float a[H2];
    for (int k = c; k < H2; k += HH)
        a[k] = fmaxf(vt2[g * H2 + k] * vs[k] + vsh[k], 0.f);
    __syncthreads();
    float acc = __ldg(&b[c]);
#pragma unroll 8
    for (int k = 0; k < H2; k++) acc = fmaf(a[k], __ldg(&W[k * HH + c]), acc);
    out[g * HH + c] = acc;
}

__global__ void vapply_kernel(const float* __restrict__ vt1, const float* __restrict__ vs,
                              const float* __restrict__ vsh, float* __restrict__ vf) {
    int idx = blockIdx.x * blockDim.x + threadIdx.x;
    if (idx < GG * HH) {
        int c = idx & (HH - 1);
        vf[idx] = fmaxf(vt1[idx] * vs[c] + vsh[c], 0.f);
    }
}

// ---------------------------------------------------------------------------
// Host driver
// ---------------------------------------------------------------------------
extern "C" void kernel_launch(void* const* d_in, const int* in_sizes, int n_in,
                              void* d_out, int out_size) {
    int off = (n_in > 3 && in_sizes[3] <= 4) ? 1 : 0;
    const float* x            = (const float*)d_in[0];
    const void*  ei           = d_in[1];
    const void*  batch        = d_in[2];
    const float* conv_w1      = (const float*)d_in[3 + off];
    const float* conv_b1      = (const float*)d_in[4 + off];
    const float* conv_bn_g    = (const float*)d_in[5 + off];
    const float* conv_bn_b    = (const float*)d_in[6 + off];
    const float* conv_w2      = (const float*)d_in[7 + off];
    const float* conv_b2      = (const float*)d_in[8 + off];
    const float* bn_g         = (const float*)d_in[9 + off];
    const float* bn_b         = (const float*)d_in[10 + off];
    const float* vn_emb       = (const float*)d_in[11 + off];
    const float* vmlp_w1      = (const float*)d_in[12 + off];
    const float* vmlp_b1      = (const float*)d_in[13 + off];
    const float* vmlp_bn1_g   = (const float*)d_in[14 + off];
    const float* vmlp_bn1_b   = (const float*)d_in[15 + off];
    const float* vmlp_w2      = (const float*)d_in[16 + off];
    const float* vmlp_b2      = (const float*)d_in[17 + off];
    const float* vmlp_bn2_g   = (const float*)d_in[18 + off];
    const float* vmlp_bn2_b   = (const float*)d_in[19 + off];

    float* out = (float*)d_out;
    float* out_feats = out;
    float* out_readout = out + (size_t)NN * HH;
    float* out_vf = out_readout + GG * HH;

    float *p_z, *p_h, *p_t, *p_u, *p_f, *p_colsum, *p_colsq, *p_scaleA, *p_shiftA,
          *p_scaleB, *p_shiftB, *p_vf, *p_pooled, *p_vt2, *p_vt1, *p_counts,
          *p_vscale, *p_vshift;
    int* p_is64;
    cudaGetSymbolAddress((void**)&p_z, g_z);
    cudaGetSymbolAddress((void**)&p_h, g_h);
    cudaGetSymbolAddress((void**)&p_t, g_t);
    cudaGetSymbolAddress((void**)&p_u, g_u);
    cudaGetSymbolAddress((void**)&p_f, g_f);
    cudaGetSymbolAddress((void**)&p_colsum, g_colsum);
    cudaGetSymbolAddress((void**)&p_colsq, g_colsq);
    cudaGetSymbolAddress((void**)&p_scaleA, g_scaleA);
    cudaGetSymbolAddress((void**)&p_shiftA, g_shiftA);
    cudaGetSymbolAddress((void**)&p_scaleB, g_scaleB);
    cudaGetSymbolAddress((void**)&p_shiftB, g_shiftB);
    cudaGetSymbolAddress((void**)&p_vf, g_vf);
    cudaGetSymbolAddress((void**)&p_pooled, g_pooled);
    cudaGetSymbolAddress((void**)&p_vt2, g_vt2);
    cudaGetSymbolAddress((void**)&p_vt1, g_vt1);
    cudaGetSymbolAddress((void**)&p_counts, g_counts);
    cudaGetSymbolAddress((void**)&p_vscale, g_vscale);
    cudaGetSymbolAddress((void**)&p_vshift, g_vshift);
    cudaGetSymbolAddress((void**)&p_is64, g_is64);

    const int M = NN;
    const float invN = 1.0f / (float)NN;
    const float invG = 1.0f / (float)GG;
    dim3 gemm_grid1((M + 127) / 128, H2 / 128);
    dim3 gemm_grid2((M + 127) / 128, HH / 128);
    int ew_blocks = (NN * (HH / 4) + 255) / 256;
    int sc_blocks = ((EE / 8) + 7) / 8;     // 8 edges per warp, 8 warps/block

    detect_kernel<<<1, 1024>>>((const int*)ei, p_is64);
    init_kernel<<<(GG * HH + 255) / 256, 256>>>(vn_emb, out_readout, p_vf, p_pooled,
                                                p_counts, p_colsum, p_colsq);
    copyz_kernel<<<(NN * HH / 4 + 255) / 256, 256>>>(x, p_z);

    for (int l = 0; l < LL; l++) {
        const float* w1 = conv_w1 + (size_t)l * HH * H2;
        const float* b1 = conv_b1 + l * H2;
        const float* cg = conv_bn_g + l * H2;
        const float* cb = conv_bn_b + l * H2;
        const float* w2 = conv_w2 + (size_t)l * H2 * HH;
        const float* b2 = conv_b2 + l * HH;
        const float* og = bn_g + l * HH;
        const float* ob = bn_b + l * HH;

        const float* hsrc = (l == 0) ? x : p_h;
        scatter_kernel<<<sc_blocks, 256>>>(hsrc, p_z, ei, EE, p_is64);

        // GEMM1 (+fused stats) -> finalize
        gemm_kernel<false><<<gemm_grid1, 256>>>(p_z, w1, b1, p_t, M, HH, H2,
                                                nullptr, nullptr, p_colsum, p_colsq);
        bn_finalize_kernel<<<1, 256>>>(p_colsum, p_colsq, cg, cb, p_scaleA, p_shiftA,
                                       H2, invN);

        // GEMM2 with fused BN+ReLU on A-load (+fused stats) -> finalize
        gemm_kernel<true><<<gemm_grid2, 256>>>(p_t, w2, b2, p_u, M, H2, HH,
                                               p_scaleA, p_shiftA, p_colsum, p_colsq);
        bn_finalize_kernel<<<1, 256>>>(p_colsum, p_colsq, og, ob, p_scaleB, p_shiftB,
                                       HH, invN);

        if (l == 0) {
            prep0_kernel<<<ew_blocks, 256>>>(p_u, p_scaleB, p_shiftB, vn_emb, p_h, p_z);
        } else if (l == 1) {
            fin1_kernel<<<ew_blocks, 256>>>(p_u, p_scaleB, p_shiftB, p_f, batch, p_pooled,
                                            p_is64);
            vgemm1_kernel<<<GG, H2>>>(p_pooled, p_vf, vmlp_w1, vmlp_b1, p_vt2);
            colstats_kernel<H2><<<64, H2>>>(p_vt2, GG, p_colsum, p_colsq);
            bn_finalize_kernel<<<1, 256>>>(p_colsum, p_colsq, vmlp_bn1_g, vmlp_bn1_b,
                                           p_vscale, p_vshift, H2, invG);
            vgemm2_kernel<<<GG, HH>>>(p_vt2, p_vscale, p_vshift, vmlp_w2, vmlp_b2, p_vt1);
            colstats_kernel<HH><<<64, HH>>>(p_vt1, GG, p_colsum, p_colsq);
            bn_finalize_kernel<<<1, 256>>>(p_colsum, p_colsq, vmlp_bn2_g, vmlp_bn2_b,
                                           p_vscale, p_vshift, HH, invG);
            vapply_kernel<<<(GG * HH + 255) / 256, 256>>>(p_vt1, p_vscale, p_vshift, p_vf);
            prep1_kernel<<<ew_blocks, 256>>>(p_f, p_vf, batch, p_h, p_z, p_is64);
        } else {
            fin2_kernel<<<ew_blocks, 256>>>(p_u, p_scaleB, p_shiftB, out_feats, batch,
                                            out_readout, p_counts, p_is64);
        }
    }

    epilogue_kernel<<<(GG * HH + 255) / 256, 256>>>(out_readout, p_counts, p_vf, out_vf);
    (void)in_sizes; (void)n_in; (void)out_size;
}